// round 10
// baseline (speedup 1.0000x reference)
#include <cuda_runtime.h>
#include <cuda_bf16.h>
#include <math.h>
#include <stdint.h>

#define L 256
#define CH 32
#define DEPTH 4
#define PLANE (L*L)
#define BUF_ELEMS (32u*CH*PLANE)

// Activation ping-pong buffers. Format: hi plane (32 bf16 = 64B per pixel)
// at offset 0, lo plane at offset LO_OFF. Pixel index = (b<<16)+(y<<8)+x.
#define LO_OFF 134217728u          // 128 MB
__device__ float g_bufA[BUF_ELEMS];   // 256 MB
__device__ float g_bufB[BUF_ELEMS];

// ---------------- helpers ----------------

__device__ __forceinline__ uint32_t smem_u32(const void* p) {
    uint32_t a;
    asm("{ .reg .u64 t; cvta.to.shared.u64 t, %1; cvt.u32.u64 %0, t; }" : "=r"(a) : "l"(p));
    return a;
}

__device__ __forceinline__ float gelu_f(float v) {
    return 0.5f * v * (1.0f + erff(v * 0.7071067811865476f));
}

__device__ __forceinline__ void ldm_x4(uint32_t* r, uint32_t addr) {
    asm volatile("ldmatrix.sync.aligned.m8n8.x4.shared.b16 {%0,%1,%2,%3}, [%4];"
        : "=r"(r[0]), "=r"(r[1]), "=r"(r[2]), "=r"(r[3]) : "r"(addr));
}

__device__ __forceinline__ void mma_bf16(float* d, const uint32_t* a, const uint32_t* b) {
    asm volatile("mma.sync.aligned.m16n8k16.row.col.f32.bf16.bf16.f32 "
        "{%0,%1,%2,%3}, {%4,%5,%6,%7}, {%8,%9}, {%0,%1,%2,%3};"
        : "+f"(d[0]), "+f"(d[1]), "+f"(d[2]), "+f"(d[3])
        : "r"(a[0]), "r"(a[1]), "r"(a[2]), "r"(a[3]), "r"(b[0]), "r"(b[1]));
}

// split v into hi/lo bf16 pair
__device__ __forceinline__ void split2(float v0, float v1, uint32_t& hi, uint32_t& lo) {
    __nv_bfloat162 h, l;
    h.x = __float2bfloat16(v0); h.y = __float2bfloat16(v1);
    l.x = __float2bfloat16(v0 - __bfloat162float(h.x));
    l.y = __float2bfloat16(v1 - __bfloat162float(h.y));
    hi = *reinterpret_cast<uint32_t*>(&h);
    lo = *reinterpret_cast<uint32_t*>(&l);
}

// ---------------- k_mid_mma: implicit-conv tensor-core middle layer ----------------
// CTA tile 16x16 px. Halo smem: position stride 80 B (64 data + 16 pad),
// row stride 1440 B, hi at H0, lo at H1.

#define CPITCH 80
#define RPITCH 1440
#define BPITCH 208
#define H0_OFF 0
#define H1_OFF 25920                  // 18*1440
#define B0_OFF 51840
#define B1_OFF 58496
#define BIAS_OFF 65152
#define SMEM_TOTAL 65344

__global__ void __launch_bounds__(256, 2)
k_mid_mma(const float* __restrict__ wa_g, const float* __restrict__ wb_g,
          const float* __restrict__ wc_g, const float* __restrict__ bias_g,
          int layer, int dir)
{
    extern __shared__ char smc[];
    float* bias_s = (float*)(smc + BIAS_OFF);
    uint32_t smem_base = smem_u32(smc);

    const char* srcC = (const char*)(dir ? g_bufB : g_bufA);
    char*       dstC = (char*)(dir ? g_bufA : g_bufB);

    int tid = threadIdx.x;
    int wid = tid >> 5;
    int lane = tid & 31;
    int tx0 = blockIdx.x * 16, ty0 = blockIdx.y * 16, bb = blockIdx.z;

    // -------- weights: split bf16 hi/lo, [o][kk] kk = class*32 + ch --------
    {
        const float* wc = wc_g + layer * 1024;
        const float* wb = wb_g + layer * 1024;
        const float* wa = wa_g + layer * 1024;
        char* B0c = smc + B0_OFF;
        char* B1c = smc + B1_OFF;
        for (int idx = tid; idx < 96 * 32; idx += 256) {
            int o = idx & 31, kk = idx >> 5;
            const float* ws = (kk < 32) ? wc : (kk < 64) ? wb : wa;
            float v = ws[(o << 5) + (kk & 31)];
            __nv_bfloat16 h0 = __float2bfloat16(v);
            float r = v - __bfloat162float(h0);
            *reinterpret_cast<__nv_bfloat16*>(B0c + o * BPITCH + kk * 2) = h0;
            *reinterpret_cast<__nv_bfloat16*>(B1c + o * BPITCH + kk * 2) = __float2bfloat16(r);
        }
        if (tid < 32) bias_s[tid] = bias_g[layer * 32 + tid];
    }

    // -------- halo copy: pure memcpy, 16B chunks, 4 lanes per position --------
    {
        for (int idx = tid; idx < 324 * 4; idx += 256) {
            int pos = idx >> 2, j = idx & 3;
            int r = pos / 18, c = pos - r * 18;
            int gy = (ty0 + r + 255) & 255;
            int gx = (tx0 + c + 255) & 255;
            uint32_t g = (((uint32_t)(bb << 16) + (gy << 8) + gx) << 6) + (j << 4);
            uint4 hv = *reinterpret_cast<const uint4*>(srcC + g);
            uint4 lv = *reinterpret_cast<const uint4*>(srcC + LO_OFF + g);
            uint32_t s = (uint32_t)(r * RPITCH + c * CPITCH + (j << 4));
            *reinterpret_cast<uint4*>(smc + s) = hv;
            *reinterpret_cast<uint4*>(smc + H1_OFF + s) = lv;
        }
    }
    __syncthreads();

    // -------- MMA mainloop (unchanged) --------
    float acc[2][4][4] = {};
    int pr0 = wid << 1;
    int hr0 = pr0 + 1;
    uint32_t laneA = (uint32_t)((lane & 15) * CPITCH + (lane >> 4) * 16);
    uint32_t aB  = smem_base + B0_OFF
                 + (uint32_t)(((((lane >> 4) << 3) + (lane & 7)) * BPITCH) + ((lane >> 3) & 1) * 16);
    uint32_t aBl = aB + (B1_OFF - B0_OFF);

    #pragma unroll
    for (int kc = 0; kc < 2; kc++) {
        uint32_t bh[3][8], bl[3][8];
        #pragma unroll
        for (int cls = 0; cls < 3; cls++) {
            uint32_t kb = (uint32_t)(cls * 64 + kc * 32);
            ldm_x4(bh[cls],     aB  + kb);
            ldm_x4(bh[cls] + 4, aB  + kb + 16 * BPITCH);
            ldm_x4(bl[cls],     aBl + kb);
            ldm_x4(bl[cls] + 4, aBl + kb + 16 * BPITCH);
        }

        auto do3 = [&](int t, int cls, const uint32_t* ah, const uint32_t* al) {
            #pragma unroll
            for (int nt = 0; nt < 4; nt++) mma_bf16(acc[t][nt], ah, &bh[cls][nt * 2]);
            #pragma unroll
            for (int nt = 0; nt < 4; nt++) mma_bf16(acc[t][nt], al, &bh[cls][nt * 2]);
            #pragma unroll
            for (int nt = 0; nt < 4; nt++) mma_bf16(acc[t][nt], ah, &bl[cls][nt * 2]);
        };

        #pragma unroll
        for (int r = 0; r < 4; r++) {
            #pragma unroll
            for (int d = 0; d < 3; d++) {
                uint32_t a0 = smem_base + H0_OFF
                            + (uint32_t)((hr0 - 1 + r) * RPITCH + d * CPITCH + kc * 32) + laneA;
                uint32_t ah[4], al[4];
                ldm_x4(ah, a0);
                ldm_x4(al, a0 + (H1_OFF - H0_OFF));
                if (r <= 2) {
                    const int dy = r - 1;
                    const int cls = (dy == 0 && d == 1) ? 0 : ((dy == 0 || d == 1) ? 1 : 2);
                    do3(0, cls, ah, al);
                }
                if (r >= 1) {
                    const int dy = r - 2;
                    const int cls = (dy == 0 && d == 1) ? 0 : ((dy == 0 || d == 1) ? 1 : 2);
                    do3(1, cls, ah, al);
                }
            }
        }
    }

    // -------- epilogue: bias + gelu, split-bf16 store to pixel records --------
    {
        int r = lane >> 2, c2 = (lane & 3) << 1;
        #pragma unroll
        for (int t = 0; t < 2; t++) {
            uint32_t rowBase = ((uint32_t)(bb << 16) + ((ty0 + pr0 + t) << 8) + tx0) << 6;
            uint32_t pA = rowBase + (uint32_t)(r << 6);
            uint32_t pB = rowBase + (uint32_t)((r + 8) << 6);
            #pragma unroll
            for (int nt = 0; nt < 4; nt++) {
                int o = (nt << 3) + c2;
                float b0 = bias_s[o], b1 = bias_s[o + 1];
                float vA0 = gelu_f(acc[t][nt][0] + b0);
                float vA1 = gelu_f(acc[t][nt][1] + b1);
                float vB0 = gelu_f(acc[t][nt][2] + b0);
                float vB1 = gelu_f(acc[t][nt][3] + b1);
                uint32_t hA, lA, hB, lB;
                split2(vA0, vA1, hA, lA);
                split2(vB0, vB1, hB, lB);
                *reinterpret_cast<uint32_t*>(dstC + pA + o * 2)          = hA;
                *reinterpret_cast<uint32_t*>(dstC + LO_OFF + pA + o * 2) = lA;
                *reinterpret_cast<uint32_t*>(dstC + pB + o * 2)          = hB;
                *reinterpret_cast<uint32_t*>(dstC + LO_OFF + pB + o * 2) = lB;
            }
        }
    }
}

// ---------------- kernel 1: first layer (1 -> 32 ch) + gelu, split format out ----------------
__global__ void k_first(const float* __restrict__ x,
                        const float* __restrict__ ci, const float* __restrict__ bi,
                        const float* __restrict__ ai, const float* __restrict__ bias_i,
                        float sign)
{
    __shared__ float w[128];
    int tid = threadIdx.y * 32 + threadIdx.x;
    if (tid < 128) {
        w[tid] = (tid < 32) ? ci[tid]
               : (tid < 64) ? bi[tid - 32]
               : (tid < 96) ? ai[tid - 64]
                            : bias_i[tid - 96];
    }
    __syncthreads();

    int gx = blockIdx.x * 32 + threadIdx.x;
    int gy = blockIdx.y * 8  + threadIdx.y;
    int b  = blockIdx.z;

    const float* xb = x + (b << 16);
    int xm = (gx + 255) & 255, xq = (gx + 1) & 255;
    int ym = (gy + 255) & 255, yq = (gy + 1) & 255;

    float ctr = xb[(gy << 8) + gx];
    float nb  = xb[(ym << 8) + gx] + xb[(yq << 8) + gx]
              + xb[(gy << 8) + xm] + xb[(gy << 8) + xq];
    float dg  = xb[(ym << 8) + xm] + xb[(ym << 8) + xq]
              + xb[(yq << 8) + xm] + xb[(yq << 8) + xq];
    ctr *= sign; nb *= sign; dg *= sign;

    uint32_t hi[16], lo[16];
    #pragma unroll
    for (int o2 = 0; o2 < 16; o2++) {
        int o = o2 * 2;
        float v0 = gelu_f(w[o] * ctr + w[32 + o] * nb + w[64 + o] * dg + w[96 + o]);
        float v1 = gelu_f(w[o+1] * ctr + w[32 + o+1] * nb + w[64 + o+1] * dg + w[96 + o+1]);
        split2(v0, v1, hi[o2], lo[o2]);
    }
    char* dstC = (char*)g_bufA;
    uint32_t p = ((uint32_t)(b << 16) + (gy << 8) + gx) << 6;
    #pragma unroll
    for (int j = 0; j < 4; j++) {
        *reinterpret_cast<uint4*>(dstC + p + j * 16) =
            make_uint4(hi[j*4], hi[j*4+1], hi[j*4+2], hi[j*4+3]);
        *reinterpret_cast<uint4*>(dstC + LO_OFF + p + j * 16) =
            make_uint4(lo[j*4], lo[j*4+1], lo[j*4+2], lo[j*4+3]);
    }
}

// ---------------- kernel 3: last layer (32 -> 1 ch), split format in ----------------
#define HS1 (32*340)
__global__ void k_last(const float* __restrict__ co, const float* __restrict__ bo,
                       const float* __restrict__ ao, float* __restrict__ out, int mode)
{
    __shared__ float Hs[HS1];      // [ch][340] planar, halo 10r x 34c
    __shared__ float ws[96];
    int tx = threadIdx.x, ty = threadIdx.y;
    int tid = ty * 32 + tx;
    int tx0 = blockIdx.x * 32, ty0 = blockIdx.y * 8, b = blockIdx.z;
    const char* srcC = (const char*)g_bufA;

    // halo: 340 positions x 4 chunks; reconstruct fp32 = hi + lo, planar STS
    for (int idx = tid; idx < 340 * 4; idx += 256) {
        int pos = idx >> 2, j = idx & 3;
        int r = pos / 34, cc = pos - r * 34;
        int gy = (ty0 + r + 255) & 255;
        int gx = (tx0 + cc + 255) & 255;
        uint32_t g = (((uint32_t)(b << 16) + (gy << 8) + gx) << 6) + (j << 4);
        uint4 hv = *reinterpret_cast<const uint4*>(srcC + g);
        uint4 lv = *reinterpret_cast<const uint4*>(srcC + LO_OFF + g);
        const uint32_t* hp = &hv.x;
        const uint32_t* lp = &lv.x;
        #pragma unroll
        for (int q = 0; q < 4; q++) {
            __nv_bfloat162 h2 = *reinterpret_cast<const __nv_bfloat162*>(&hp[q]);
            __nv_bfloat162 l2 = *reinterpret_cast<const __nv_bfloat162*>(&lp[q]);
            int ch = j * 8 + q * 2;
            Hs[ch * 340 + pos]       = __bfloat162float(h2.x) + __bfloat162float(l2.x);
            Hs[(ch + 1) * 340 + pos] = __bfloat162float(h2.y) + __bfloat162float(l2.y);
        }
    }
    if (tid < 96) {
        ws[tid] = (tid < 32) ? co[tid] : (tid < 64) ? bo[tid - 32] : ao[tid - 64];
    }
    __syncthreads();

    int base = (ty + 1) * 34 + tx + 1;
    float acc = 0.f;
    #pragma unroll 4
    for (int i = 0; i < 32; i++) {
        const float* h = Hs + i * 340;
        float ctr = h[base];
        float nb  = h[base - 34] + h[base + 34] + h[base - 1]  + h[base + 1];
        float dg  = h[base - 35] + h[base + 35] + h[base - 33] + h[base + 33];
        acc += ws[i] * ctr + ws[32 + i] * nb + ws[64 + i] * dg;
    }

    int gy = ty0 + ty, gx = tx0 + tx;
    int oidx = (b << 16) + (gy << 8) + gx;
    if (mode == 0) out[oidx] = 0.5f * acc;
    else           out[oidx] -= 0.5f * acc;
}

// ---------------- launcher ----------------

extern "C" void kernel_launch(void* const* d_in, const int* in_sizes, int n_in,
                              void* d_out, int out_size)
{
    const float* x      = (const float*)d_in[0];
    const float* ai     = (const float*)d_in[1];
    const float* ao     = (const float*)d_in[2];
    const float* a      = (const float*)d_in[3];
    const float* bi     = (const float*)d_in[4];
    const float* bo     = (const float*)d_in[5];
    const float* b      = (const float*)d_in[6];
    const float* ci     = (const float*)d_in[7];
    const float* co     = (const float*)d_in[8];
    const float* c      = (const float*)d_in[9];
    const float* bias_i = (const float*)d_in[10];
    const float* bias   = (const float*)d_in[11];
    float* out = (float*)d_out;

    cudaFuncSetAttribute(k_mid_mma, cudaFuncAttributeMaxDynamicSharedMemorySize, SMEM_TOTAL);

    dim3 gridM(16, 16, 32);
    dim3 gridS(8, 32, 32);
    dim3 blkS(32, 8);

    for (int s = 0; s < 2; s++) {
        float sign = s ? -1.f : 1.f;
        k_first<<<gridS, blkS>>>(x, ci, bi, ai, bias_i, sign);
        int dir = 0;
        for (int k = 0; k < DEPTH; k++) {
            k_mid_mma<<<gridM, 256, SMEM_TOTAL>>>(a, b, c, bias, k, dir);
            dir ^= 1;
        }
        k_last<<<gridS, blkS>>>(co, bo, ao, out, s);
    }
}

// round 12
// speedup vs baseline: 1.2198x; 1.2198x over previous
#include <cuda_runtime.h>
#include <cuda_bf16.h>
#include <math.h>
#include <stdint.h>

#define L 256
#define CH 32
#define DEPTH 4
#define PLANE (L*L)
#define BUF_ELEMS (32u*CH*PLANE)

__device__ float g_bufA[BUF_ELEMS];
__device__ float g_bufB[BUF_ELEMS];

// ---------------- helpers ----------------

__device__ __forceinline__ uint32_t smem_u32(const void* p) {
    uint32_t a;
    asm("{ .reg .u64 t; cvta.to.shared.u64 t, %1; cvt.u32.u64 %0, t; }" : "=r"(a) : "l"(p));
    return a;
}

__device__ __forceinline__ float gelu_f(float v) {
    return 0.5f * v * (1.0f + erff(v * 0.7071067811865476f));
}

__device__ __forceinline__ void ldm_x4(uint32_t* r, uint32_t addr) {
    asm volatile("ldmatrix.sync.aligned.m8n8.x4.shared.b16 {%0,%1,%2,%3}, [%4];"
        : "=r"(r[0]), "=r"(r[1]), "=r"(r[2]), "=r"(r[3]) : "r"(addr));
}

__device__ __forceinline__ void mma_bf16(float* d, const uint32_t* a, const uint32_t* b) {
    asm volatile("mma.sync.aligned.m16n8k16.row.col.f32.bf16.bf16.f32 "
        "{%0,%1,%2,%3}, {%4,%5,%6,%7}, {%8,%9}, {%0,%1,%2,%3};"
        : "+f"(d[0]), "+f"(d[1]), "+f"(d[2]), "+f"(d[3])
        : "r"(a[0]), "r"(a[1]), "r"(a[2]), "r"(a[3]), "r"(b[0]), "r"(b[1]));
}

// ---------------- k_mid_mma: implicit-conv tensor-core middle layer ----------------
// CTA tile: 16x16 = 256 px. D[256 p][32 o] = sum over 9 offsets of
//   Halo[p+off][32 ch] x Bclass(off)[32 o][32 ch]^T  (split-bf16, 3 products)
// Halo channel-contiguous: position stride 80 B, row stride 1440 B.
// Class-major mainloop: hold B frags for one class (16 regs), reload A per
// class-position -> regs fit 3 CTAs/SM.

#define CPITCH 80
#define RPITCH 1440
#define BPITCH 208
#define H0_OFF 0
#define H1_OFF 25920                  // 18*1440
#define B0_OFF 51840
#define B1_OFF 58496                  // +32*208
#define BIAS_OFF 65152
#define SMEM_TOTAL 65344

__global__ void __launch_bounds__(256, 3)
k_mid_mma(const float* __restrict__ wa_g, const float* __restrict__ wb_g,
          const float* __restrict__ wc_g, const float* __restrict__ bias_g,
          int layer, int dir)
{
    extern __shared__ char smc[];
    float* bias_s = (float*)(smc + BIAS_OFF);
    uint32_t smem_base = smem_u32(smc);

    const float* src = dir ? g_bufB : g_bufA;
    float*       dst = dir ? g_bufA : g_bufB;

    int tid = threadIdx.x;
    int wid = tid >> 5;
    int lane = tid & 31;
    int tx0 = blockIdx.x * 16, ty0 = blockIdx.y * 16, bb = blockIdx.z;

    // -------- weights: split bf16 hi/lo, [o][kk] kk = class*32 + ch --------
    {
        const float* wc = wc_g + layer * 1024;
        const float* wb = wb_g + layer * 1024;
        const float* wa = wa_g + layer * 1024;
        char* B0c = smc + B0_OFF;
        char* B1c = smc + B1_OFF;
        for (int idx = tid; idx < 96 * 32; idx += 256) {
            int o = idx & 31, kk = idx >> 5;
            const float* ws = (kk < 32) ? wc : (kk < 64) ? wb : wa;
            float v = ws[(o << 5) + (kk & 31)];
            __nv_bfloat16 h0 = __float2bfloat16(v);
            float r = v - __bfloat162float(h0);
            *reinterpret_cast<__nv_bfloat16*>(B0c + o * BPITCH + kk * 2) = h0;
            *reinterpret_cast<__nv_bfloat16*>(B1c + o * BPITCH + kk * 2) = __float2bfloat16(r);
        }
        if (tid < 32) bias_s[tid] = bias_g[layer * 32 + tid];
    }

    // -------- halo load + split-bf16 store, channel-contiguous --------
    {
        const float* inb = src + ((bb * CH) << 16);
        for (int t = tid; t < 324; t += 256) {
            int r = t / 18, c = t - r * 18;
            int gy = (ty0 + r + 255) & 255;
            int gx = (tx0 + c + 255) & 255;
            const float* g = inb + (gy << 8) + gx;
            char* h0 = smc + H0_OFF + r * RPITCH + c * CPITCH;
            char* h1 = smc + H1_OFF + r * RPITCH + c * CPITCH;
            #pragma unroll
            for (int ch2 = 0; ch2 < 16; ch2++) {
                float v0 = g[(ch2 * 2) << 16];
                float v1 = g[(ch2 * 2 + 1) << 16];
                __nv_bfloat16 a0 = __float2bfloat16(v0);
                __nv_bfloat16 a1 = __float2bfloat16(v1);
                __nv_bfloat162 hi; hi.x = a0; hi.y = a1;
                __nv_bfloat162 lo;
                lo.x = __float2bfloat16(v0 - __bfloat162float(a0));
                lo.y = __float2bfloat16(v1 - __bfloat162float(a1));
                *reinterpret_cast<__nv_bfloat162*>(h0 + ch2 * 4) = hi;
                *reinterpret_cast<__nv_bfloat162*>(h1 + ch2 * 4) = lo;
            }
        }
    }
    __syncthreads();

    // -------- MMA mainloop (class-major, low register pressure) --------
    // Warp owns target tile rows pr0, pr0+1; physical halo row for (t, dy=r-1)
    // is pr0 + t + r.  acc[t] = 16px x 32o for row pr0+t.
    float acc[2][4][4] = {};
    int pr0 = wid << 1;
    uint32_t laneA = (uint32_t)((lane & 15) * CPITCH + (lane >> 4) * 16);
    uint32_t aB  = smem_base + B0_OFF
                 + (uint32_t)(((((lane >> 4) << 3) + (lane & 7)) * BPITCH) + ((lane >> 3) & 1) * 16);
    uint32_t aBl = aB + (B1_OFF - B0_OFF);

    #pragma unroll
    for (int kc = 0; kc < 2; kc++) {
        #pragma unroll
        for (int cls = 0; cls < 3; cls++) {
            uint32_t bh[8], bl[8];
            uint32_t kb = (uint32_t)(cls * 64 + kc * 32);
            ldm_x4(bh,     aB  + kb);
            ldm_x4(bh + 4, aB  + kb + 16 * BPITCH);
            ldm_x4(bl,     aBl + kb);
            ldm_x4(bl + 4, aBl + kb + 16 * BPITCH);

            #pragma unroll
            for (int t = 0; t < 2; t++) {
                #pragma unroll
                for (int r = 0; r < 3; r++) {
                    #pragma unroll
                    for (int d = 0; d < 3; d++) {
                        const int dy = r - 1;
                        const int c = (dy == 0 && d == 1) ? 0 : ((dy == 0 || d == 1) ? 1 : 2);
                        if (c != cls) continue;
                        uint32_t a0 = smem_base + H0_OFF
                                    + (uint32_t)((pr0 + t + r) * RPITCH + d * CPITCH + kc * 32)
                                    + laneA;
                        uint32_t ah[4], al[4];
                        ldm_x4(ah, a0);
                        ldm_x4(al, a0 + (H1_OFF - H0_OFF));
                        #pragma unroll
                        for (int nt = 0; nt < 4; nt++) mma_bf16(acc[t][nt], ah, &bh[nt * 2]);
                        #pragma unroll
                        for (int nt = 0; nt < 4; nt++) mma_bf16(acc[t][nt], al, &bh[nt * 2]);
                        #pragma unroll
                        for (int nt = 0; nt < 4; nt++) mma_bf16(acc[t][nt], ah, &bl[nt * 2]);
                    }
                }
            }
        }
    }

    // -------- epilogue: bias + gelu, direct sector-aligned STG --------
    {
        int r = lane >> 2, c2 = (lane & 3) << 1;
        #pragma unroll
        for (int nt = 0; nt < 4; nt++) {
            int o = (nt << 3) + c2;
            float b0 = bias_s[o], b1 = bias_s[o + 1];
            #pragma unroll
            for (int t = 0; t < 2; t++) {
                float* bp = dst + ((uint32_t)(bb * CH + o) << 16)
                          + ((uint32_t)(ty0 + pr0 + t) << 8) + tx0;
                bp[r]             = gelu_f(acc[t][nt][0] + b0);
                bp[65536 + r]     = gelu_f(acc[t][nt][1] + b1);
                bp[r + 8]         = gelu_f(acc[t][nt][2] + b0);
                bp[65536 + r + 8] = gelu_f(acc[t][nt][3] + b1);
            }
        }
    }
}

// ---------------- kernel 1: first layer (1 -> 32 ch) + gelu ----------------
__global__ void k_first(const float* __restrict__ x,
                        const float* __restrict__ ci, const float* __restrict__ bi,
                        const float* __restrict__ ai, const float* __restrict__ bias_i,
                        float sign)
{
    __shared__ float w[128];
    int tid = threadIdx.y * 32 + threadIdx.x;
    if (tid < 128) {
        w[tid] = (tid < 32) ? ci[tid]
               : (tid < 64) ? bi[tid - 32]
               : (tid < 96) ? ai[tid - 64]
                            : bias_i[tid - 96];
    }
    __syncthreads();

    int gx = blockIdx.x * 32 + threadIdx.x;
    int gy = blockIdx.y * 8  + threadIdx.y;
    int b  = blockIdx.z;

    const float* xb = x + (b << 16);
    int xm = (gx + 255) & 255, xq = (gx + 1) & 255;
    int ym = (gy + 255) & 255, yq = (gy + 1) & 255;

    float ctr = xb[(gy << 8) + gx];
    float nb  = xb[(ym << 8) + gx] + xb[(yq << 8) + gx]
              + xb[(gy << 8) + xm] + xb[(gy << 8) + xq];
    float dg  = xb[(ym << 8) + xm] + xb[(ym << 8) + xq]
              + xb[(yq << 8) + xm] + xb[(yq << 8) + xq];
    ctr *= sign; nb *= sign; dg *= sign;

    float* outp = g_bufA + ((b * CH) << 16) + (gy << 8) + gx;
    #pragma unroll
    for (int o = 0; o < 32; o++) {
        float v = w[o] * ctr + w[32 + o] * nb + w[64 + o] * dg + w[96 + o];
        outp[o << 16] = gelu_f(v);
    }
}

// ---------------- kernel 3: last layer (32 -> 1 ch), antisym combine ----------------
#define HS1 (32*10*34)
__global__ void k_last(const float* __restrict__ co, const float* __restrict__ bo,
                       const float* __restrict__ ao, float* __restrict__ out, int mode)
{
    __shared__ float Hs[HS1];
    __shared__ float ws[96];
    int tx = threadIdx.x, ty = threadIdx.y;
    int tid = ty * 32 + tx;
    int tx0 = blockIdx.x * 32, ty0 = blockIdx.y * 8, b = blockIdx.z;
    const float* inb = g_bufA + ((b * CH) << 16);

    for (int t = tid; t < HS1; t += 256) {
        int i   = t / 340;
        int rem = t - i * 340;
        int r   = rem / 34;
        int cc  = rem - r * 34;
        int gy  = (ty0 + r + 255) & 255;
        int gx  = (tx0 + cc + 255) & 255;
        Hs[t] = inb[(i << 16) + (gy << 8) + gx];
    }
    if (tid < 96) {
        ws[tid] = (tid < 32) ? co[tid] : (tid < 64) ? bo[tid - 32] : ao[tid - 64];
    }
    __syncthreads();

    int base = (ty + 1) * 34 + tx + 1;
    float acc = 0.f;
    #pragma unroll 4
    for (int i = 0; i < 32; i++) {
        const float* h = Hs + i * 340;
        float ctr = h[base];
        float nb  = h[base - 34] + h[base + 34] + h[base - 1]  + h[base + 1];
        float dg  = h[base - 35] + h[base + 35] + h[base - 33] + h[base + 33];
        acc += ws[i] * ctr + ws[32 + i] * nb + ws[64 + i] * dg;
    }

    int gy = ty0 + ty, gx = tx0 + tx;
    int oidx = (b << 16) + (gy << 8) + gx;
    if (mode == 0) out[oidx] = 0.5f * acc;
    else           out[oidx] -= 0.5f * acc;
}

// ---------------- launcher ----------------

extern "C" void kernel_launch(void* const* d_in, const int* in_sizes, int n_in,
                              void* d_out, int out_size)
{
    const float* x      = (const float*)d_in[0];
    const float* ai     = (const float*)d_in[1];
    const float* ao     = (const float*)d_in[2];
    const float* a      = (const float*)d_in[3];
    const float* bi     = (const float*)d_in[4];
    const float* bo     = (const float*)d_in[5];
    const float* b      = (const float*)d_in[6];
    const float* ci     = (const float*)d_in[7];
    const float* co     = (const float*)d_in[8];
    const float* c      = (const float*)d_in[9];
    const float* bias_i = (const float*)d_in[10];
    const float* bias   = (const float*)d_in[11];
    float* out = (float*)d_out;

    cudaFuncSetAttribute(k_mid_mma, cudaFuncAttributeMaxDynamicSharedMemorySize, SMEM_TOTAL);

    dim3 gridM(16, 16, 32);     // 16x16 px tiles
    dim3 gridS(8, 32, 32);
    dim3 blkS(32, 8);

    for (int s = 0; s < 2; s++) {
        float sign = s ? -1.f : 1.f;
        k_first<<<gridS, blkS>>>(x, ci, bi, ai, bias_i, sign);
        int dir = 0;
        for (int k = 0; k < DEPTH; k++) {
            k_mid_mma<<<gridM, 256, SMEM_TOTAL>>>(a, b, c, bias, k, dir);
            dir ^= 1;
        }
        k_last<<<gridS, blkS>>>(co, bo, ao, out, s);
    }
}

// round 13
// speedup vs baseline: 1.3609x; 1.1157x over previous
#include <cuda_runtime.h>
#include <cuda_bf16.h>
#include <math.h>
#include <stdint.h>

#define L 256
#define CH 32
#define DEPTH 4
#define PLANE (L*L)
#define BUF_ELEMS (32u*CH*PLANE)

__device__ float g_bufA[BUF_ELEMS];
__device__ float g_bufB[BUF_ELEMS];

// ---------------- helpers ----------------

__device__ __forceinline__ uint32_t smem_u32(const void* p) {
    uint32_t a;
    asm("{ .reg .u64 t; cvta.to.shared.u64 t, %1; cvt.u32.u64 %0, t; }" : "=r"(a) : "l"(p));
    return a;
}

__device__ __forceinline__ float gelu_f(float v) {
    return 0.5f * v * (1.0f + erff(v * 0.7071067811865476f));
}

__device__ __forceinline__ void ldm_x4(uint32_t* r, uint32_t addr) {
    asm volatile("ldmatrix.sync.aligned.m8n8.x4.shared.b16 {%0,%1,%2,%3}, [%4];"
        : "=r"(r[0]), "=r"(r[1]), "=r"(r[2]), "=r"(r[3]) : "r"(addr));
}

__device__ __forceinline__ void mma_bf16(float* d, const uint32_t* a, const uint32_t* b) {
    asm volatile("mma.sync.aligned.m16n8k16.row.col.f32.bf16.bf16.f32 "
        "{%0,%1,%2,%3}, {%4,%5,%6,%7}, {%8,%9}, {%0,%1,%2,%3};"
        : "+f"(d[0]), "+f"(d[1]), "+f"(d[2]), "+f"(d[3])
        : "r"(a[0]), "r"(a[1]), "r"(a[2]), "r"(a[3]), "r"(b[0]), "r"(b[1]));
}

// ---------------- k_mid_mma: implicit-conv tensor-core middle layer ----------------
// CTA tile: 16x16 = 256 px. Phase-pair mainloop: cls1 B resident per kc;
// cls0/cls2 time-share one register slot. Every A fragment loaded once,
// feeds both target rows (t=0,1).

#define CPITCH 80
#define RPITCH 1440
#define BPITCH 208
#define H0_OFF 0
#define H1_OFF 25920                  // 18*1440
#define B0_OFF 51840
#define B1_OFF 58496                  // +32*208
#define BIAS_OFF 65152
#define SMEM_TOTAL 65344

__global__ void __launch_bounds__(256, 3)
k_mid_mma(const float* __restrict__ wa_g, const float* __restrict__ wb_g,
          const float* __restrict__ wc_g, const float* __restrict__ bias_g,
          int layer, int dir)
{
    extern __shared__ char smc[];
    float* bias_s = (float*)(smc + BIAS_OFF);
    uint32_t smem_base = smem_u32(smc);

    const float* src = dir ? g_bufB : g_bufA;
    float*       dst = dir ? g_bufA : g_bufB;

    int tid = threadIdx.x;
    int wid = tid >> 5;
    int lane = tid & 31;
    int tx0 = blockIdx.x * 16, ty0 = blockIdx.y * 16, bb = blockIdx.z;

    // -------- weights: split bf16 hi/lo, [o][kk] kk = class*32 + ch --------
    {
        const float* wc = wc_g + layer * 1024;
        const float* wb = wb_g + layer * 1024;
        const float* wa = wa_g + layer * 1024;
        char* B0c = smc + B0_OFF;
        char* B1c = smc + B1_OFF;
        for (int idx = tid; idx < 96 * 32; idx += 256) {
            int o = idx & 31, kk = idx >> 5;
            const float* ws = (kk < 32) ? wc : (kk < 64) ? wb : wa;
            float v = ws[(o << 5) + (kk & 31)];
            __nv_bfloat16 h0 = __float2bfloat16(v);
            float r = v - __bfloat162float(h0);
            *reinterpret_cast<__nv_bfloat16*>(B0c + o * BPITCH + kk * 2) = h0;
            *reinterpret_cast<__nv_bfloat16*>(B1c + o * BPITCH + kk * 2) = __float2bfloat16(r);
        }
        if (tid < 32) bias_s[tid] = bias_g[layer * 32 + tid];
    }

    // -------- halo load + split-bf16 store, channel-contiguous --------
    {
        const float* inb = src + ((bb * CH) << 16);
        for (int t = tid; t < 324; t += 256) {
            int r = t / 18, c = t - r * 18;
            int gy = (ty0 + r + 255) & 255;
            int gx = (tx0 + c + 255) & 255;
            const float* g = inb + (gy << 8) + gx;
            char* h0 = smc + H0_OFF + r * RPITCH + c * CPITCH;
            char* h1 = smc + H1_OFF + r * RPITCH + c * CPITCH;
            #pragma unroll
            for (int ch2 = 0; ch2 < 16; ch2++) {
                float v0 = g[(ch2 * 2) << 16];
                float v1 = g[(ch2 * 2 + 1) << 16];
                __nv_bfloat16 a0 = __float2bfloat16(v0);
                __nv_bfloat16 a1 = __float2bfloat16(v1);
                __nv_bfloat162 hi; hi.x = a0; hi.y = a1;
                __nv_bfloat162 lo;
                lo.x = __float2bfloat16(v0 - __bfloat162float(a0));
                lo.y = __float2bfloat16(v1 - __bfloat162float(a1));
                *reinterpret_cast<__nv_bfloat162*>(h0 + ch2 * 4) = hi;
                *reinterpret_cast<__nv_bfloat162*>(h1 + ch2 * 4) = lo;
            }
        }
    }
    __syncthreads();

    // -------- MMA mainloop (phase-pair, shared A fragments) --------
    // Warp owns target rows pr0, pr0+1; A fragment at physical row pr0+R, dx d
    // serves t=0 if R<=2 (dy=R-1), t=1 if R>=1 (dy=R-2).
    float acc[2][4][4] = {};
    int pr0 = wid << 1;
    uint32_t laneA = (uint32_t)((lane & 15) * CPITCH + (lane >> 4) * 16);
    uint32_t aB  = smem_base + B0_OFF
                 + (uint32_t)(((((lane >> 4) << 3) + (lane & 7)) * BPITCH) + ((lane >> 3) & 1) * 16);
    uint32_t aBl = aB + (B1_OFF - B0_OFF);

    #pragma unroll
    for (int kc = 0; kc < 2; kc++) {
        uint32_t bhS[8], blS[8];     // time-shared: cls0 in phase A, cls2 in phase B
        uint32_t bh1[8], bl1[8];     // cls1 resident

        uint32_t kb0 = (uint32_t)(kc * 32);
        ldm_x4(bhS,     aB  + kb0);                       // cls0
        ldm_x4(bhS + 4, aB  + kb0 + 16 * BPITCH);
        ldm_x4(blS,     aBl + kb0);
        ldm_x4(blS + 4, aBl + kb0 + 16 * BPITCH);
        uint32_t kb1 = (uint32_t)(64 + kc * 32);
        ldm_x4(bh1,     aB  + kb1);                       // cls1
        ldm_x4(bh1 + 4, aB  + kb1 + 16 * BPITCH);
        ldm_x4(bl1,     aBl + kb1);
        ldm_x4(bl1 + 4, aBl + kb1 + 16 * BPITCH);

        auto do3 = [&](int t, bool useS, const uint32_t* ah, const uint32_t* al) {
            const uint32_t* bh = useS ? bhS : bh1;
            const uint32_t* bl = useS ? blS : bl1;
            #pragma unroll
            for (int nt = 0; nt < 4; nt++) mma_bf16(acc[t][nt], ah, &bh[nt * 2]);
            #pragma unroll
            for (int nt = 0; nt < 4; nt++) mma_bf16(acc[t][nt], al, &bh[nt * 2]);
            #pragma unroll
            for (int nt = 0; nt < 4; nt++) mma_bf16(acc[t][nt], ah, &bl[nt * 2]);
        };

        // ---- phase A: d = 1 (classes 0 and 1) ----
        #pragma unroll
        for (int R = 0; R < 4; R++) {
            uint32_t a0 = smem_base + H0_OFF
                        + (uint32_t)((pr0 + R) * RPITCH + 1 * CPITCH + kc * 32) + laneA;
            uint32_t ah[4], al[4];
            ldm_x4(ah, a0);
            ldm_x4(al, a0 + (H1_OFF - H0_OFF));
            if (R <= 2) do3(0, (R == 1), ah, al);   // dy=R-1: 0 -> cls0
            if (R >= 1) do3(1, (R == 2), ah, al);   // dy=R-2: 0 -> cls0
        }

        // ---- switch shared slot to cls2 ----
        uint32_t kb2 = (uint32_t)(128 + kc * 32);
        ldm_x4(bhS,     aB  + kb2);
        ldm_x4(bhS + 4, aB  + kb2 + 16 * BPITCH);
        ldm_x4(blS,     aBl + kb2);
        ldm_x4(blS + 4, aBl + kb2 + 16 * BPITCH);

        // ---- phase B: d = 0 and d = 2 (classes 1 and 2) ----
        #pragma unroll
        for (int dd = 0; dd < 2; dd++) {
            const int d = dd * 2;
            #pragma unroll
            for (int R = 0; R < 4; R++) {
                uint32_t a0 = smem_base + H0_OFF
                            + (uint32_t)((pr0 + R) * RPITCH + d * CPITCH + kc * 32) + laneA;
                uint32_t ah[4], al[4];
                ldm_x4(ah, a0);
                ldm_x4(al, a0 + (H1_OFF - H0_OFF));
                if (R <= 2) do3(0, (R != 1), ah, al);   // dy=0 -> cls1, else cls2(S)
                if (R >= 1) do3(1, (R != 2), ah, al);
            }
        }
    }

    // -------- epilogue: bias + gelu, direct sector-aligned STG --------
    {
        int r = lane >> 2, c2 = (lane & 3) << 1;
        #pragma unroll
        for (int nt = 0; nt < 4; nt++) {
            int o = (nt << 3) + c2;
            float b0 = bias_s[o], b1 = bias_s[o + 1];
            #pragma unroll
            for (int t = 0; t < 2; t++) {
                float* bp = dst + ((uint32_t)(bb * CH + o) << 16)
                          + ((uint32_t)(ty0 + pr0 + t) << 8) + tx0;
                bp[r]             = gelu_f(acc[t][nt][0] + b0);
                bp[65536 + r]     = gelu_f(acc[t][nt][1] + b1);
                bp[r + 8]         = gelu_f(acc[t][nt][2] + b0);
                bp[65536 + r + 8] = gelu_f(acc[t][nt][3] + b1);
            }
        }
    }
}

// ---------------- kernel 1: first layer (1 -> 32 ch) + gelu ----------------
__global__ void k_first(const float* __restrict__ x,
                        const float* __restrict__ ci, const float* __restrict__ bi,
                        const float* __restrict__ ai, const float* __restrict__ bias_i,
                        float sign)
{
    __shared__ float w[128];
    int tid = threadIdx.y * 32 + threadIdx.x;
    if (tid < 128) {
        w[tid] = (tid < 32) ? ci[tid]
               : (tid < 64) ? bi[tid - 32]
               : (tid < 96) ? ai[tid - 64]
                            : bias_i[tid - 96];
    }
    __syncthreads();

    int gx = blockIdx.x * 32 + threadIdx.x;
    int gy = blockIdx.y * 8  + threadIdx.y;
    int b  = blockIdx.z;

    const float* xb = x + (b << 16);
    int xm = (gx + 255) & 255, xq = (gx + 1) & 255;
    int ym = (gy + 255) & 255, yq = (gy + 1) & 255;

    float ctr = xb[(gy << 8) + gx];
    float nb  = xb[(ym << 8) + gx] + xb[(yq << 8) + gx]
              + xb[(gy << 8) + xm] + xb[(gy << 8) + xq];
    float dg  = xb[(ym << 8) + xm] + xb[(ym << 8) + xq]
              + xb[(yq << 8) + xm] + xb[(yq << 8) + xq];
    ctr *= sign; nb *= sign; dg *= sign;

    float* outp = g_bufA + ((b * CH) << 16) + (gy << 8) + gx;
    #pragma unroll
    for (int o = 0; o < 32; o++) {
        float v = w[o] * ctr + w[32 + o] * nb + w[64 + o] * dg + w[96 + o];
        outp[o << 16] = gelu_f(v);
    }
}

// ---------------- kernel 3: last layer (32 -> 1 ch), antisym combine ----------------
#define HS1 (32*10*34)
__global__ void k_last(const float* __restrict__ co, const float* __restrict__ bo,
                       const float* __restrict__ ao, float* __restrict__ out, int mode)
{
    __shared__ float Hs[HS1];
    __shared__ float ws[96];
    int tx = threadIdx.x, ty = threadIdx.y;
    int tid = ty * 32 + tx;
    int tx0 = blockIdx.x * 32, ty0 = blockIdx.y * 8, b = blockIdx.z;
    const float* inb = g_bufA + ((b * CH) << 16);

    for (int t = tid; t < HS1; t += 256) {
        int i   = t / 340;
        int rem = t - i * 340;
        int r   = rem / 34;
        int cc  = rem - r * 34;
        int gy  = (ty0 + r + 255) & 255;
        int gx  = (tx0 + cc + 255) & 255;
        Hs[t] = inb[(i << 16) + (gy << 8) + gx];
    }
    if (tid < 96) {
        ws[tid] = (tid < 32) ? co[tid] : (tid < 64) ? bo[tid - 32] : ao[tid - 64];
    }
    __syncthreads();

    int base = (ty + 1) * 34 + tx + 1;
    float acc = 0.f;
    #pragma unroll 4
    for (int i = 0; i < 32; i++) {
        const float* h = Hs + i * 340;
        float ctr = h[base];
        float nb  = h[base - 34] + h[base + 34] + h[base - 1]  + h[base + 1];
        float dg  = h[base - 35] + h[base + 35] + h[base - 33] + h[base + 33];
        acc += ws[i] * ctr + ws[32 + i] * nb + ws[64 + i] * dg;
    }

    int gy = ty0 + ty, gx = tx0 + tx;
    int oidx = (b << 16) + (gy << 8) + gx;
    if (mode == 0) out[oidx] = 0.5f * acc;
    else           out[oidx] -= 0.5f * acc;
}

// ---------------- launcher ----------------

extern "C" void kernel_launch(void* const* d_in, const int* in_sizes, int n_in,
                              void* d_out, int out_size)
{
    const float* x      = (const float*)d_in[0];
    const float* ai     = (const float*)d_in[1];
    const float* ao     = (const float*)d_in[2];
    const float* a      = (const float*)d_in[3];
    const float* bi     = (const float*)d_in[4];
    const float* bo     = (const float*)d_in[5];
    const float* b      = (const float*)d_in[6];
    const float* ci     = (const float*)d_in[7];
    const float* co     = (const float*)d_in[8];
    const float* c      = (const float*)d_in[9];
    const float* bias_i = (const float*)d_in[10];
    const float* bias   = (const float*)d_in[11];
    float* out = (float*)d_out;

    cudaFuncSetAttribute(k_mid_mma, cudaFuncAttributeMaxDynamicSharedMemorySize, SMEM_TOTAL);

    dim3 gridM(16, 16, 32);     // 16x16 px tiles
    dim3 gridS(8, 32, 32);
    dim3 blkS(32, 8);

    for (int s = 0; s < 2; s++) {
        float sign = s ? -1.f : 1.f;
        k_first<<<gridS, blkS>>>(x, ci, bi, ai, bias_i, sign);
        int dir = 0;
        for (int k = 0; k < DEPTH; k++) {
            k_mid_mma<<<gridM, 256, SMEM_TOTAL>>>(a, b, c, bias, k, dir);
            dir ^= 1;
        }
        k_last<<<gridS, blkS>>>(co, bo, ao, out, s);
    }
}